// round 1
// baseline (speedup 1.0000x reference)
#include <cuda_runtime.h>

#define BS 8
#define CI 256
#define CO 256
#define HH 128
#define WW 128
#define EPSV 1e-6f

#define CO_TILE 32
#define ROWS 8
#define COLS 64
#define XROWS 10      // ROWS + 2 halo
#define XCOLS 66      // COLS + 2 halo
#define XPITCH 72     // padded pitch
#define XTOT (XROWS*XCOLS)   // 660

// scratch (no cudaMalloc allowed)
__device__ float g_wt[CI * CO * 5];     // weights transposed to [ci][co][s]
__device__ float g_demod[BS * CO];      // d[b,o]

// ---------------- prologue: transpose weights [o][ci][5] -> [ci][co][5] ----------------
__global__ void transpose_w_kernel(const float* __restrict__ w) {
    int ci = blockIdx.x;
    int o = threadIdx.x;
#pragma unroll
    for (int s = 0; s < 5; s++)
        g_wt[(ci * CO + o) * 5 + s] = w[(o * CI + ci) * 5 + s];
}

// ---------------- prologue: demod d[b,o] = rsqrt(sum_ci m^2 * sum_s w^2 + eps) ----------
__global__ void demod_kernel(const float* __restrict__ y, const float* __restrict__ w) {
    int o = blockIdx.x;
    int b = blockIdx.y;
    int ci = threadIdx.x;
    float m = 1.0f + y[b * CI + ci];
    const float* wr = w + (o * CI + ci) * 5;
    float s = wr[0]*wr[0] + wr[1]*wr[1] + wr[2]*wr[2] + wr[3]*wr[3] + wr[4]*wr[4];
    float v = m * m * s;
#pragma unroll
    for (int off = 16; off; off >>= 1) v += __shfl_xor_sync(0xffffffffu, v, off);
    __shared__ float red[8];
    if ((threadIdx.x & 31) == 0) red[threadIdx.x >> 5] = v;
    __syncthreads();
    if (threadIdx.x == 0) {
        float t = red[0]+red[1]+red[2]+red[3]+red[4]+red[5]+red[6]+red[7];
        g_demod[b * CO + o] = rsqrtf(t + EPSV);
    }
}

// ---------------- main conv: 5-tap stencil, weights batch-shared, m folded into x -------
__global__ __launch_bounds__(256, 2) void conv_main_kernel(
    const float* __restrict__ x, const float* __restrict__ y, float* __restrict__ out)
{
    __shared__ float xs[2][XROWS * XPITCH];
    __shared__ float ws[2][CO_TILE * 5];
    __shared__ float ms[CI];

    const int tid  = threadIdx.x;
    const int lane = tid & 31;
    const int wrp  = tid >> 5;
    const int colseg = wrp & 1;   // which 32-col segment
    const int cog    = wrp >> 1;  // which group of 8 output channels

    const int tileid = blockIdx.x;
    const int r0 = (tileid >> 1) * ROWS;
    const int c0 = (tileid & 1) * COLS;
    const int o0 = blockIdx.y * CO_TILE;
    const int b  = blockIdx.z;

    ms[tid] = 1.0f + y[b * CI + tid];
    __syncthreads();

    // precompute prefetch addressing (per-thread, ci-invariant)
    int soff[3], goff[3];
    bool ok[3], st[3];
#pragma unroll
    for (int i = 0; i < 3; i++) {
        int idx = tid + i * 256;
        int r = idx / XCOLS, c = idx % XCOLS;
        st[i]   = (idx < XTOT);
        soff[i] = r * XPITCH + c;
        int gr = r0 - 1 + r, gc = c0 - 1 + c;
        ok[i]   = st[i] && (gr >= 0) && (gr < HH) && (gc >= 0) && (gc < WW);
        goff[i] = ok[i] ? (gr * WW + gc) : 0;
    }

    const float* xg = x + (long long)b * CI * HH * WW;

    // load ci = 0 into buffer 0
    {
        float v[3];
#pragma unroll
        for (int i = 0; i < 3; i++) v[i] = ok[i] ? xg[goff[i]] : 0.0f;
        float m0 = ms[0];
#pragma unroll
        for (int i = 0; i < 3; i++) if (st[i]) xs[0][soff[i]] = v[i] * m0;
        if (tid < CO_TILE * 5) ws[0][tid] = g_wt[(0 * CO + o0) * 5 + tid];
    }
    __syncthreads();

    float acc[64];
#pragma unroll
    for (int i = 0; i < 64; i++) acc[i] = 0.0f;

    const int cc = colseg * 32 + lane;  // tile column 0..63

    int cur = 0;
    for (int ci = 0; ci < CI; ci++) {
        const bool more = (ci + 1 < CI);
        float v[3] = {0.f, 0.f, 0.f};
        float wv = 0.f;
        if (more) {
            const float* xp = xg + (long long)(ci + 1) * HH * WW;
#pragma unroll
            for (int i = 0; i < 3; i++) v[i] = ok[i] ? xp[goff[i]] : 0.0f;
            if (tid < CO_TILE * 5) wv = g_wt[((ci + 1) * CO + o0) * 5 + tid];
        }

        // compute from current buffer
        const float* xb = xs[cur];
        float xc[10], xl[8], xr[8];
#pragma unroll
        for (int k = 0; k < 10; k++) xc[k] = xb[k * XPITCH + cc + 1];
#pragma unroll
        for (int k = 0; k < 8; k++) {
            xl[k] = xb[(k + 1) * XPITCH + cc];
            xr[k] = xb[(k + 1) * XPITCH + cc + 2];
        }
        const float* wb = ws[cur];
#pragma unroll
        for (int j = 0; j < 8; j++) {
            const int cj = (cog * 8 + j) * 5;
            const float w0 = wb[cj + 0];
            const float w1 = wb[cj + 1];
            const float w2 = wb[cj + 2];
            const float w3 = wb[cj + 3];
            const float w4 = wb[cj + 4];
#pragma unroll
            for (int k = 0; k < 8; k++) {
                float a = acc[j * 8 + k];
                a = fmaf(w0, xc[k],     a);   // top    (h-1, w)
                a = fmaf(w1, xl[k],     a);   // left   (h, w-1)
                a = fmaf(w2, xc[k + 1], a);   // center (h, w)
                a = fmaf(w3, xr[k],     a);   // right  (h, w+1)
                a = fmaf(w4, xc[k + 2], a);   // bottom (h+1, w)
                acc[j * 8 + k] = a;
            }
        }

        if (more) {
            float mm = ms[ci + 1];
#pragma unroll
            for (int i = 0; i < 3; i++) if (st[i]) xs[cur ^ 1][soff[i]] = v[i] * mm;
            if (tid < CO_TILE * 5) ws[cur ^ 1][tid] = wv;
        }
        __syncthreads();
        cur ^= 1;
    }

    // epilogue: scale by d[b,o] and store (lane = column -> coalesced)
#pragma unroll
    for (int j = 0; j < 8; j++) {
        const int o = o0 + cog * 8 + j;
        const float ds = g_demod[b * CO + o];
        float* op = out + ((long long)(b * CO + o) * HH + r0) * WW + c0 + cc;
#pragma unroll
        for (int k = 0; k < 8; k++)
            op[k * WW] = acc[j * 8 + k] * ds;
    }
}

extern "C" void kernel_launch(void* const* d_in, const int* in_sizes, int n_in,
                              void* d_out, int out_size) {
    const float* x = (const float*)d_in[0];
    const float* y = (const float*)d_in[1];
    const float* w = (const float*)d_in[2];
    // d_in[3] = stencil_index (fixed plus-stencil [1,3,4,5,7]; hardcoded in tap mapping)
    float* out = (float*)d_out;

    transpose_w_kernel<<<CI, CO>>>(w);
    demod_kernel<<<dim3(CO, BS), CI>>>(y, w);

    dim3 grid((HH / ROWS) * (WW / COLS), CO / CO_TILE, BS);
    conv_main_kernel<<<grid, 256>>>(x, y, out);
}